// round 4
// baseline (speedup 1.0000x reference)
#include <cuda_runtime.h>
#include <cstdint>
#include <cstddef>

#define NN   50000
#define EE   600000
#define DD   128
#define OUTD 64

// ---------------------------------------------------------------------------
// Scratch state (no allocations allowed -> __device__ globals)
// ---------------------------------------------------------------------------
__device__ int   g_counts[NN];
__device__ int   g_cursor[NN];
__device__ int   g_rowoff[NN + 1];
__device__ int   g_csrsrc[EE];
__device__ float g_deg[NN];        // in-degree per node (float)
__device__ float g_sdeg[NN];       // s = A(deg)
__device__ float g_bufA[(size_t)NN * DD];
__device__ float g_bufB[(size_t)NN * DD];
__device__ float g_Wsq1[DD * DD];  // W1 @ W1
__device__ float g_Wsq2[DD * DD];  // W2 @ W2
__device__ float g_bW1[DD];        // b1 @ W1
__device__ float g_bW2[DD];        // b2 @ W2
__device__ int   g_is32;           // 1 if edge_index is int32, 0 if int64

// ---------------------------------------------------------------------------
// Setup kernels
// ---------------------------------------------------------------------------
__global__ void k_init() {
    int i = blockIdx.x * blockDim.x + threadIdx.x;
    if (i < NN) { g_counts[i] = 0; g_cursor[i] = 0; }
    if (i == 0) g_is32 = 0;   // default assumption: int64
}

// edge_index was requested as int64 in the reference, but default JAX produces
// int32. int64 little-endian => every high 32-bit word is 0. If any sampled
// odd word is nonzero, the buffer must be int32.
__global__ void k_detect(const int* __restrict__ w) {
    int i = blockIdx.x * blockDim.x + threadIdx.x;
    if (i < 4096) {
        if (w[2 * i + 1] != 0) g_is32 = 1;
    }
}

__device__ __forceinline__ int load_edge(const void* ei, int idx, int is32) {
    if (is32) return ((const int*)ei)[idx];
    return (int)((const long long*)ei)[idx];
}

__global__ void k_count(const void* __restrict__ ei) {
    int e = blockIdx.x * blockDim.x + threadIdx.x;
    if (e >= EE) return;
    int is32 = g_is32;
    int dst = load_edge(ei, EE + e, is32);
    if ((unsigned)dst < (unsigned)NN)
        atomicAdd(&g_counts[dst], 1);
}

// single-block exclusive scan of g_counts -> g_rowoff; also g_deg = counts
__global__ void k_scan() {
    __shared__ int wsum[32];
    __shared__ int running_s;
    int tid = threadIdx.x;
    int lane = tid & 31, wid = tid >> 5;
    if (tid == 0) running_s = 0;
    __syncthreads();
    for (int base = 0; base < NN; base += 1024) {
        int i = base + tid;
        int v = (i < NN) ? g_counts[i] : 0;
        int x = v;
        #pragma unroll
        for (int o = 1; o < 32; o <<= 1) {
            int t = __shfl_up_sync(0xffffffffu, x, o);
            if (lane >= o) x += t;
        }
        if (lane == 31) wsum[wid] = x;
        __syncthreads();
        if (wid == 0) {
            int y = wsum[lane];
            #pragma unroll
            for (int o = 1; o < 32; o <<= 1) {
                int t = __shfl_up_sync(0xffffffffu, y, o);
                if (lane >= o) y += t;
            }
            wsum[lane] = y;
        }
        __syncthreads();
        int incl = x + (wid ? wsum[wid - 1] : 0);
        int excl = incl - v + running_s;
        if (i < NN) {
            g_rowoff[i] = excl;
            g_deg[i] = (float)v;
        }
        __syncthreads();
        if (tid == 0) running_s += wsum[31];
        __syncthreads();
    }
    if (threadIdx.x == 0) g_rowoff[NN] = running_s;
}

__global__ void k_fill(const void* __restrict__ ei) {
    int e = blockIdx.x * blockDim.x + threadIdx.x;
    if (e >= EE) return;
    int is32 = g_is32;
    int src = load_edge(ei, e, is32);
    int dst = load_edge(ei, EE + e, is32);
    if ((unsigned)dst >= (unsigned)NN) return;
    if ((unsigned)src >= (unsigned)NN) src = 0;
    int pos = g_rowoff[dst] + atomicAdd(&g_cursor[dst], 1);
    g_csrsrc[pos] = src;
}

__global__ void k_sdeg() {
    int i = blockIdx.x * blockDim.x + threadIdx.x;
    if (i >= NN) return;
    int beg = g_rowoff[i], end = g_rowoff[i + 1];
    float s = 0.f;
    for (int e = beg; e < end; ++e) s += g_deg[g_csrsrc[e]];
    g_sdeg[i] = s;
}

// Wsq[r][c] = sum_k W[r][k] * W[k][c]     (128x128, tiny)
__global__ void k_matsq(const float* __restrict__ W, float* __restrict__ Wsq) {
    int idx = blockIdx.x * blockDim.x + threadIdx.x;
    if (idx >= DD * DD) return;
    int r = idx >> 7, c = idx & 127;
    float s = 0.f;
    #pragma unroll 8
    for (int k = 0; k < DD; ++k) s += W[r * DD + k] * W[k * DD + c];
    Wsq[idx] = s;
}

// bW[c] = sum_k b[k] * W[k][c]
__global__ void k_bw(const float* __restrict__ b, const float* __restrict__ W,
                     float* __restrict__ bw) {
    int c = threadIdx.x;
    if (c >= DD) return;
    float s = 0.f;
    #pragma unroll 8
    for (int k = 0; k < DD; ++k) s += b[k] * W[k * DD + c];
    bw[c] = s;
}

// ---------------------------------------------------------------------------
// Aggregation: out[i][:] = sum over incoming edges of in[src][:]
// One warp per node, each lane owns one float4 (4 cols) of the 128-col row.
// ---------------------------------------------------------------------------
__global__ void __launch_bounds__(256) k_agg(const float* __restrict__ in,
                                             float* __restrict__ out) {
    int w = (blockIdx.x * blockDim.x + threadIdx.x) >> 5;
    int lane = threadIdx.x & 31;
    if (w >= NN) return;
    int beg = g_rowoff[w], end = g_rowoff[w + 1];
    const float4* base = (const float4*)in;
    float4 acc = make_float4(0.f, 0.f, 0.f, 0.f);
    int e = beg;
    for (; e + 2 <= end; e += 2) {
        int s0 = g_csrsrc[e];
        int s1 = g_csrsrc[e + 1];
        float4 v0 = base[(size_t)s0 * 32 + lane];
        float4 v1 = base[(size_t)s1 * 32 + lane];
        acc.x += v0.x + v1.x;
        acc.y += v0.y + v1.y;
        acc.z += v0.z + v1.z;
        acc.w += v0.w + v1.w;
    }
    if (e < end) {
        int s0 = g_csrsrc[e];
        float4 v0 = base[(size_t)s0 * 32 + lane];
        acc.x += v0.x; acc.y += v0.y; acc.z += v0.z; acc.w += v0.w;
    }
    ((float4*)out)[(size_t)w * 32 + lane] = acc;
}

// ---------------------------------------------------------------------------
// SGEMM: C[N x NCOL] = A[N x 128] @ W[128 x NCOL] (+ epilogue)
//   POOL=true : C = relu(A@W + s_r * bw[c] + d_r * bv[c])
//   POOL=false: C = A@W + bv[c]
// Block: 128 rows x NCOL cols, 256 threads, 8 x (NCOL/16) register tile.
// ---------------------------------------------------------------------------
template <int NCOL, bool POOL>
__global__ void __launch_bounds__(256, 1)
k_gemm(const float* __restrict__ A, const float* __restrict__ W,
       const float* __restrict__ sv, const float* __restrict__ dv,
       const float* __restrict__ bw, const float* __restrict__ bv,
       float* __restrict__ C) {
    constexpr int CPT = NCOL / 16;   // cols per thread: 8 (NCOL=128) or 4 (64)
    extern __shared__ float sm[];
    float* Asm = sm;               // [128 rows][128 k]
    float* Wsm = sm + 128 * 128;   // [128 k][NCOL]

    const int tid = threadIdx.x;
    const int row0 = blockIdx.x * 128;

    // load W tile (always fully valid)
    {
        const float4* Wg = (const float4*)W;
        float4* Ws4 = (float4*)Wsm;
        constexpr int tot = 128 * NCOL / 4;
        #pragma unroll
        for (int i = tid; i < tot; i += 256) Ws4[i] = Wg[i];
    }
    // load A tile (row-guarded, zero pad)
    {
        const float4* Ag = (const float4*)A;
        float4* As4 = (float4*)Asm;
        #pragma unroll
        for (int it = 0; it < 16; ++it) {
            int idx = it * 256 + tid;          // 0..4095
            int r = idx >> 5, kq = idx & 31;
            float4 v = make_float4(0.f, 0.f, 0.f, 0.f);
            if (row0 + r < NN) v = Ag[(size_t)(row0 + r) * 32 + kq];
            As4[r * 32 + kq] = v;
        }
    }
    __syncthreads();

    const int ty = tid >> 4, tx = tid & 15;
    const int rb = ty * 8;
    const int cb = tx * CPT;

    float acc[8][CPT];
    #pragma unroll
    for (int i = 0; i < 8; ++i)
        #pragma unroll
        for (int j = 0; j < CPT; ++j) acc[i][j] = 0.f;

    #pragma unroll 4
    for (int k = 0; k < 128; ++k) {
        float a[8];
        #pragma unroll
        for (int i = 0; i < 8; ++i) a[i] = Asm[(rb + i) * 128 + k];
        float b[CPT];
        const float4* Wk = (const float4*)(Wsm + k * NCOL + cb);
        #pragma unroll
        for (int j4 = 0; j4 < CPT / 4; ++j4) {
            float4 bb = Wk[j4];
            b[j4 * 4 + 0] = bb.x; b[j4 * 4 + 1] = bb.y;
            b[j4 * 4 + 2] = bb.z; b[j4 * 4 + 3] = bb.w;
        }
        #pragma unroll
        for (int i = 0; i < 8; ++i)
            #pragma unroll
            for (int j = 0; j < CPT; ++j)
                acc[i][j] += a[i] * b[j];
    }

    // epilogue
    #pragma unroll
    for (int i = 0; i < 8; ++i) {
        int r = row0 + rb + i;
        if (r >= NN) continue;
        float sr = 0.f, dr = 0.f;
        if (POOL) { sr = sv[r]; dr = dv[r]; }
        #pragma unroll
        for (int j0 = 0; j0 < CPT; j0 += 4) {
            float4 o;
            float* op = &o.x;
            #pragma unroll
            for (int q = 0; q < 4; ++q) {
                int c = cb + j0 + q;
                float v = acc[i][j0 + q];
                if (POOL) {
                    v += sr * bw[c] + dr * bv[c];
                    v = fmaxf(v, 0.f);
                } else {
                    v += bv[c];
                }
                op[q] = v;
            }
            *(float4*)&C[(size_t)r * NCOL + cb + j0] = o;
        }
    }
}

// ---------------------------------------------------------------------------
// Launch
// ---------------------------------------------------------------------------
extern "C" void kernel_launch(void* const* d_in, const int* in_sizes, int n_in,
                              void* d_out, int out_size) {
    const float* x    = (const float*)d_in[0];
    const void*  ei   = d_in[1];
    const float* W1   = (const float*)d_in[2];
    const float* b1   = (const float*)d_in[3];
    const float* W2   = (const float*)d_in[4];
    const float* b2   = (const float*)d_in[5];
    const float* Wout = (const float*)d_in[6];
    const float* bout = (const float*)d_in[7];
    float* out = (float*)d_out;

    void *pA, *pB, *pWsq1, *pWsq2, *pbW1, *pbW2, *pdeg, *psdeg;
    cudaGetSymbolAddress(&pA, g_bufA);
    cudaGetSymbolAddress(&pB, g_bufB);
    cudaGetSymbolAddress(&pWsq1, g_Wsq1);
    cudaGetSymbolAddress(&pWsq2, g_Wsq2);
    cudaGetSymbolAddress(&pbW1, g_bW1);
    cudaGetSymbolAddress(&pbW2, g_bW2);
    cudaGetSymbolAddress(&pdeg, g_deg);
    cudaGetSymbolAddress(&psdeg, g_sdeg);
    float* bufA = (float*)pA;
    float* bufB = (float*)pB;
    float* Wsq1 = (float*)pWsq1;
    float* Wsq2 = (float*)pWsq2;
    float* bW1  = (float*)pbW1;
    float* bW2  = (float*)pbW2;
    float* degv = (float*)pdeg;
    float* sdeg = (float*)psdeg;

    const size_t SMEM128 = (128 * 128 + 128 * 128) * sizeof(float);  // 128 KB
    const size_t SMEM64  = (128 * 128 + 128 * 64) * sizeof(float);   //  96 KB
    cudaFuncSetAttribute(k_gemm<128, true>,
                         cudaFuncAttributeMaxDynamicSharedMemorySize, (int)SMEM128);
    cudaFuncSetAttribute(k_gemm<64, false>,
                         cudaFuncAttributeMaxDynamicSharedMemorySize, (int)SMEM64);

    const int GN  = (NN + 255) / 256;
    const int GE  = (EE + 255) / 256;
    const int GAG = (NN * 32 + 255) / 256;       // one warp per node
    const int GGM = (NN + 127) / 128;

    // ---- CSR build + precompute ----
    k_init<<<GN, 256>>>();
    k_detect<<<16, 256>>>((const int*)ei);
    k_count<<<GE, 256>>>(ei);
    k_scan<<<1, 1024>>>();
    k_fill<<<GE, 256>>>(ei);
    k_sdeg<<<GN, 256>>>();
    k_matsq<<<(DD * DD + 255) / 256, 256>>>(W1, Wsq1);
    k_matsq<<<(DD * DD + 255) / 256, 256>>>(W2, Wsq2);
    k_bw<<<1, 128>>>(b1, W1, bW1);
    k_bw<<<1, 128>>>(b2, W2, bW2);

    // ---- Block 1: h1 = relu(A^2(x) @ W1^2 + s*(b1@W1) + d*b1) ----
    k_agg<<<GAG, 256>>>(x, bufA);
    k_agg<<<GAG, 256>>>(bufA, bufB);
    k_gemm<128, true><<<GGM, 256, SMEM128>>>(bufB, Wsq1, sdeg, degv, bW1, b1, bufA);

    // ---- Block 2: h2 = relu(A^2(h1) @ W2^2 + s*(b2@W2) + d*b2) ----
    k_agg<<<GAG, 256>>>(bufA, bufB);
    k_agg<<<GAG, 256>>>(bufB, bufA);
    k_gemm<128, true><<<GGM, 256, SMEM128>>>(bufA, Wsq2, sdeg, degv, bW2, b2, bufB);

    // ---- Output: out = h2 @ Wout + bout ----
    k_gemm<64, false><<<GGM, 256, SMEM64>>>(bufB, Wout, nullptr, nullptr,
                                            nullptr, bout, out);
}

// round 6
// speedup vs baseline: 1.0877x; 1.0877x over previous
#include <cuda_runtime.h>
#include <cstdint>
#include <cstddef>

#define NN   50000
#define EE   600000
#define DD   128
#define OUTD 64
#define NB   ((NN + 255) / 256)   // 196 scan blocks

// ---------------------------------------------------------------------------
// Scratch state (no allocations allowed -> __device__ globals)
// ---------------------------------------------------------------------------
__device__ int   g_counts[NN];
__device__ int   g_cursor[NN];
__device__ int   g_rowoff[NN + 1];
__device__ int   g_bsum[NB];
__device__ int   g_csrsrc[EE];
__device__ float g_deg[NN];
__device__ float g_sdeg[NN];
__device__ float g_bufA[(size_t)NN * DD];
__device__ float g_bufB[(size_t)NN * DD];
__device__ float g_Wsq1[DD * DD];
__device__ float g_Wsq2[DD * DD];
__device__ float g_bW1[DD];
__device__ float g_bW2[DD];
__device__ float2 g_Whl1[DD * DD];    // split(W1@W1): (tf32-hi, tf32-lo)
__device__ float2 g_Whl2[DD * DD];    // split(W2@W2)
__device__ float2 g_WhlO[DD * OUTD];  // split(Wout)
__device__ int   g_is32;

// ---------------------------------------------------------------------------
// tf32 split + mma helpers
// ---------------------------------------------------------------------------
__device__ __forceinline__ void split_tf32(float x, unsigned& hi, unsigned& lo) {
    unsigned h;
    asm("cvt.rna.tf32.f32 %0, %1;" : "=r"(h) : "f"(x));
    float r = x - __uint_as_float(h);
    unsigned l;
    asm("cvt.rna.tf32.f32 %0, %1;" : "=r"(l) : "f"(r));
    hi = h; lo = l;
}

__device__ __forceinline__ void mma_tf32(float c[4], const unsigned a[4],
                                         unsigned b0, unsigned b1) {
    asm volatile(
        "mma.sync.aligned.m16n8k8.row.col.f32.tf32.tf32.f32 "
        "{%0,%1,%2,%3}, {%4,%5,%6,%7}, {%8,%9}, {%0,%1,%2,%3};"
        : "+f"(c[0]), "+f"(c[1]), "+f"(c[2]), "+f"(c[3])
        : "r"(a[0]), "r"(a[1]), "r"(a[2]), "r"(a[3]), "r"(b0), "r"(b1));
}

// ---------------------------------------------------------------------------
// Setup kernels
// ---------------------------------------------------------------------------
__global__ void k_init() {
    int i = blockIdx.x * blockDim.x + threadIdx.x;
    if (i < NN) { g_counts[i] = 0; g_cursor[i] = 0; }
    if (i == 0) g_is32 = 0;
}

__global__ void k_detect(const int* __restrict__ w) {
    int i = blockIdx.x * blockDim.x + threadIdx.x;
    if (i < 4096) {
        if (w[2 * i + 1] != 0) g_is32 = 1;
    }
}

__device__ __forceinline__ int load_edge(const void* ei, int idx, int is32) {
    if (is32) return ((const int*)ei)[idx];
    return (int)((const long long*)ei)[idx];
}

__global__ void k_count(const void* __restrict__ ei) {
    int e = blockIdx.x * blockDim.x + threadIdx.x;
    if (e >= EE) return;
    int is32 = g_is32;
    int dst = load_edge(ei, EE + e, is32);
    if ((unsigned)dst < (unsigned)NN)
        atomicAdd(&g_counts[dst], 1);
}

// ---- two-level scan (replaces the 48us single-block scan) ----
__global__ void k_bsum() {
    __shared__ int ws[8];
    int tid = threadIdx.x;
    int i = blockIdx.x * 256 + tid;
    int v = (i < NN) ? g_counts[i] : 0;
    #pragma unroll
    for (int o = 16; o > 0; o >>= 1) v += __shfl_down_sync(0xffffffffu, v, o);
    if ((tid & 31) == 0) ws[tid >> 5] = v;
    __syncthreads();
    if (tid == 0) {
        int s = 0;
        #pragma unroll
        for (int w = 0; w < 8; ++w) s += ws[w];
        g_bsum[blockIdx.x] = s;
    }
}

__global__ void k_bscan() {
    __shared__ int ws[8];
    int tid = threadIdx.x;
    int lane = tid & 31, wid = tid >> 5;
    int v = (tid < NB) ? g_bsum[tid] : 0;
    int x = v;
    #pragma unroll
    for (int o = 1; o < 32; o <<= 1) {
        int t = __shfl_up_sync(0xffffffffu, x, o);
        if (lane >= o) x += t;
    }
    if (lane == 31) ws[wid] = x;
    __syncthreads();
    if (wid == 0) {
        int y = (lane < 8) ? ws[lane] : 0;
        #pragma unroll
        for (int o = 1; o < 8; o <<= 1) {
            int t = __shfl_up_sync(0xffffffffu, y, o);
            if (lane >= o) y += t;
        }
        if (lane < 8) ws[lane] = y;
    }
    __syncthreads();
    int incl = x + (wid ? ws[wid - 1] : 0);
    if (tid < NB) g_bsum[tid] = incl - v;   // exclusive
    if (tid == NB - 1) g_rowoff[NN] = incl; // grand total
}

__global__ void k_rowoff() {
    __shared__ int ws[8];
    int tid = threadIdx.x;
    int lane = tid & 31, wid = tid >> 5;
    int i = blockIdx.x * 256 + tid;
    int v = (i < NN) ? g_counts[i] : 0;
    int x = v;
    #pragma unroll
    for (int o = 1; o < 32; o <<= 1) {
        int t = __shfl_up_sync(0xffffffffu, x, o);
        if (lane >= o) x += t;
    }
    if (lane == 31) ws[wid] = x;
    __syncthreads();
    if (wid == 0) {
        int y = (lane < 8) ? ws[lane] : 0;
        #pragma unroll
        for (int o = 1; o < 8; o <<= 1) {
            int t = __shfl_up_sync(0xffffffffu, y, o);
            if (lane >= o) y += t;
        }
        if (lane < 8) ws[lane] = y;
    }
    __syncthreads();
    int excl = x - v + (wid ? ws[wid - 1] : 0) + g_bsum[blockIdx.x];
    if (i < NN) {
        g_rowoff[i] = excl;
        g_deg[i] = (float)v;
    }
}

__global__ void k_fill(const void* __restrict__ ei) {
    int e = blockIdx.x * blockDim.x + threadIdx.x;
    if (e >= EE) return;
    int is32 = g_is32;
    int src = load_edge(ei, e, is32);
    int dst = load_edge(ei, EE + e, is32);
    if ((unsigned)dst >= (unsigned)NN) return;
    if ((unsigned)src >= (unsigned)NN) src = 0;
    int pos = g_rowoff[dst] + atomicAdd(&g_cursor[dst], 1);
    g_csrsrc[pos] = src;
}

__global__ void k_sdeg() {
    int i = blockIdx.x * blockDim.x + threadIdx.x;
    if (i >= NN) return;
    int beg = g_rowoff[i], end = g_rowoff[i + 1];
    float s = 0.f;
    for (int e = beg; e < end; ++e) s += g_deg[g_csrsrc[e]];
    g_sdeg[i] = s;
}

__global__ void k_matsq(const float* __restrict__ W, float* __restrict__ Wsq) {
    int idx = blockIdx.x * blockDim.x + threadIdx.x;
    if (idx >= DD * DD) return;
    int r = idx >> 7, c = idx & 127;
    float s = 0.f;
    #pragma unroll 8
    for (int k = 0; k < DD; ++k) s += W[r * DD + k] * W[k * DD + c];
    Wsq[idx] = s;
}

__global__ void k_bw(const float* __restrict__ b, const float* __restrict__ W,
                     float* __restrict__ bw) {
    int c = threadIdx.x;
    if (c >= DD) return;
    float s = 0.f;
    #pragma unroll 8
    for (int k = 0; k < DD; ++k) s += b[k] * W[k * DD + c];
    bw[c] = s;
}

__global__ void k_wsplit(const float* __restrict__ W, float2* __restrict__ O, int n) {
    int i = blockIdx.x * blockDim.x + threadIdx.x;
    if (i >= n) return;
    unsigned h, l;
    split_tf32(W[i], h, l);
    O[i] = make_float2(__uint_as_float(h), __uint_as_float(l));
}

// ---------------------------------------------------------------------------
// Aggregation: one warp per node, lane owns one float4 of the 128-col row.
// ---------------------------------------------------------------------------
__global__ void __launch_bounds__(256) k_agg(const float* __restrict__ in,
                                             float* __restrict__ out) {
    int w = (blockIdx.x * blockDim.x + threadIdx.x) >> 5;
    int lane = threadIdx.x & 31;
    if (w >= NN) return;
    int beg = g_rowoff[w], end = g_rowoff[w + 1];
    const float4* base = (const float4*)in;
    float4 acc = make_float4(0.f, 0.f, 0.f, 0.f);
    int e = beg;
    for (; e + 2 <= end; e += 2) {
        int s0 = g_csrsrc[e];
        int s1 = g_csrsrc[e + 1];
        float4 v0 = base[(size_t)s0 * 32 + lane];
        float4 v1 = base[(size_t)s1 * 32 + lane];
        acc.x += v0.x + v1.x;
        acc.y += v0.y + v1.y;
        acc.z += v0.z + v1.z;
        acc.w += v0.w + v1.w;
    }
    if (e < end) {
        int s0 = g_csrsrc[e];
        float4 v0 = base[(size_t)s0 * 32 + lane];
        acc.x += v0.x; acc.y += v0.y; acc.z += v0.z; acc.w += v0.w;
    }
    ((float4*)out)[(size_t)w * 32 + lane] = acc;
}

// ---------------------------------------------------------------------------
// Tensor-core GEMM (3xTF32): C[N x NCOL] = A[N x 128] @ W[128 x NCOL]
//   POOL=true : C = relu(A@W + s_r * bw[c] + d_r * bv[c])
//   POOL=false: C = A@W + bv[c]
// Block: 128 rows, 256 threads (8 warps). Warp w: rows [16w,16w+16), all cols.
// Whl holds pre-split W as float2(hi,lo) tf32 pairs, row-major [k][n].
// ---------------------------------------------------------------------------
template <int NCOL, bool POOL>
__global__ void __launch_bounds__(256, 1)
k_gemm_tc(const float* __restrict__ A, const float2* __restrict__ Whl,
          const float* __restrict__ sv, const float* __restrict__ dv,
          const float* __restrict__ bw, const float* __restrict__ bv,
          float* __restrict__ C) {
    constexpr int NT = NCOL / 8;   // n-tiles per warp
    constexpr int AS = 132;        // A smem stride (floats) -> conflict-free frags
    constexpr int WS = NCOL + 2;   // W smem stride (float2)
    extern __shared__ char smraw[];
    float*  Asm = (float*)smraw;
    float2* Wsm = (float2*)(smraw + 128 * AS * sizeof(float));

    const int tid = threadIdx.x;
    const int row0 = blockIdx.x * 128;

    // Load split W tile
    #pragma unroll 4
    for (int idx = tid; idx < 128 * NCOL; idx += 256) {
        int k = idx / NCOL, n = idx % NCOL;
        Wsm[k * WS + n] = Whl[idx];
    }
    // Load A tile (row-guarded, zero pad)
    {
        const float4* Ag = (const float4*)A;
        #pragma unroll
        for (int it = 0; it < 16; ++it) {
            int idx = it * 256 + tid;
            int r = idx >> 5, kq = idx & 31;
            float4 v = make_float4(0.f, 0.f, 0.f, 0.f);
            if (row0 + r < NN) v = Ag[(size_t)(row0 + r) * 32 + kq];
            *(float4*)(Asm + r * AS + kq * 4) = v;
        }
    }
    __syncthreads();

    const int warp = tid >> 5, lane = tid & 31;
    const int gid = lane >> 2, tig = lane & 3;
    const int r0 = warp * 16;

    float c[NT][4];
    #pragma unroll
    for (int nt = 0; nt < NT; ++nt)
        #pragma unroll
        for (int q = 0; q < 4; ++q) c[nt][q] = 0.f;

    for (int ks = 0; ks < 16; ++ks) {
        int k0 = ks * 8;
        // A fragment (m16n8k8 layout): a0=(gid,tig) a1=(gid+8,tig)
        //                              a2=(gid,tig+4) a3=(gid+8,tig+4)
        float a0f = Asm[(r0 + gid) * AS + k0 + tig];
        float a1f = Asm[(r0 + gid + 8) * AS + k0 + tig];
        float a2f = Asm[(r0 + gid) * AS + k0 + tig + 4];
        float a3f = Asm[(r0 + gid + 8) * AS + k0 + tig + 4];
        unsigned ah[4], al[4];
        split_tf32(a0f, ah[0], al[0]);
        split_tf32(a1f, ah[1], al[1]);
        split_tf32(a2f, ah[2], al[2]);
        split_tf32(a3f, ah[3], al[3]);

        const float2* W0 = Wsm + (k0 + tig) * WS;       // b0 row (k)
        const float2* W1 = Wsm + (k0 + tig + 4) * WS;   // b1 row (k+4)
        #pragma unroll
        for (int nt = 0; nt < NT; ++nt) {
            float2 b0 = W0[nt * 8 + gid];
            float2 b1 = W1[nt * 8 + gid];
            unsigned bh0 = __float_as_uint(b0.x), bl0 = __float_as_uint(b0.y);
            unsigned bh1 = __float_as_uint(b1.x), bl1 = __float_as_uint(b1.y);
            mma_tf32(c[nt], ah, bh0, bh1);   // Ah*Wh
            mma_tf32(c[nt], al, bh0, bh1);   // Al*Wh
            mma_tf32(c[nt], ah, bl0, bl1);   // Ah*Wl
        }
    }

    // Epilogue. c0/c1: row gid, cols 2tig/2tig+1; c2/c3: row gid+8.
    int rA = row0 + r0 + gid;
    int rB = rA + 8;
    float sA = 0.f, dA = 0.f, sB = 0.f, dB = 0.f;
    if (POOL) {
        if (rA < NN) { sA = sv[rA]; dA = dv[rA]; }
        if (rB < NN) { sB = sv[rB]; dB = dv[rB]; }
    }
    #pragma unroll
    for (int nt = 0; nt < NT; ++nt) {
        int col = nt * 8 + 2 * tig;
        float v0 = bv[col], v1 = bv[col + 1];
        float w0 = 0.f, w1 = 0.f;
        if (POOL) { w0 = bw[col]; w1 = bw[col + 1]; }
        if (rA < NN) {
            float x0 = c[nt][0], x1 = c[nt][1];
            if (POOL) {
                x0 = fmaxf(x0 + sA * w0 + dA * v0, 0.f);
                x1 = fmaxf(x1 + sA * w1 + dA * v1, 0.f);
            } else { x0 += v0; x1 += v1; }
            *(float2*)&C[(size_t)rA * NCOL + col] = make_float2(x0, x1);
        }
        if (rB < NN) {
            float x0 = c[nt][2], x1 = c[nt][3];
            if (POOL) {
                x0 = fmaxf(x0 + sB * w0 + dB * v0, 0.f);
                x1 = fmaxf(x1 + sB * w1 + dB * v1, 0.f);
            } else { x0 += v0; x1 += v1; }
            *(float2*)&C[(size_t)rB * NCOL + col] = make_float2(x0, x1);
        }
    }
}

// ---------------------------------------------------------------------------
// Launch
// ---------------------------------------------------------------------------
extern "C" void kernel_launch(void* const* d_in, const int* in_sizes, int n_in,
                              void* d_out, int out_size) {
    const float* x    = (const float*)d_in[0];
    const void*  ei   = d_in[1];
    const float* W1   = (const float*)d_in[2];
    const float* b1   = (const float*)d_in[3];
    const float* W2   = (const float*)d_in[4];
    const float* b2   = (const float*)d_in[5];
    const float* Wout = (const float*)d_in[6];
    const float* bout = (const float*)d_in[7];
    float* out = (float*)d_out;

    void *pA, *pB, *pWsq1, *pWsq2, *pbW1, *pbW2, *pdeg, *psdeg;
    void *pWhl1, *pWhl2, *pWhlO;
    cudaGetSymbolAddress(&pA, g_bufA);
    cudaGetSymbolAddress(&pB, g_bufB);
    cudaGetSymbolAddress(&pWsq1, g_Wsq1);
    cudaGetSymbolAddress(&pWsq2, g_Wsq2);
    cudaGetSymbolAddress(&pbW1, g_bW1);
    cudaGetSymbolAddress(&pbW2, g_bW2);
    cudaGetSymbolAddress(&pdeg, g_deg);
    cudaGetSymbolAddress(&psdeg, g_sdeg);
    cudaGetSymbolAddress(&pWhl1, g_Whl1);
    cudaGetSymbolAddress(&pWhl2, g_Whl2);
    cudaGetSymbolAddress(&pWhlO, g_WhlO);
    float*  bufA = (float*)pA;
    float*  bufB = (float*)pB;
    float*  Wsq1 = (float*)pWsq1;
    float*  Wsq2 = (float*)pWsq2;
    float*  bW1  = (float*)pbW1;
    float*  bW2  = (float*)pbW2;
    float*  degv = (float*)pdeg;
    float*  sdeg = (float*)psdeg;
    float2* Whl1 = (float2*)pWhl1;
    float2* Whl2 = (float2*)pWhl2;
    float2* WhlO = (float2*)pWhlO;

    const size_t SM128 = 128 * 132 * sizeof(float) + 128 * 130 * sizeof(float2); // 196 KB
    const size_t SM64  = 128 * 132 * sizeof(float) + 128 * 66  * sizeof(float2); // 132 KB
    cudaFuncSetAttribute(k_gemm_tc<128, true>,
                         cudaFuncAttributeMaxDynamicSharedMemorySize, (int)SM128);
    cudaFuncSetAttribute(k_gemm_tc<64, false>,
                         cudaFuncAttributeMaxDynamicSharedMemorySize, (int)SM64);

    const int GN  = (NN + 255) / 256;
    const int GE  = (EE + 255) / 256;
    const int GAG = (NN * 32 + 255) / 256;       // one warp per node
    const int GGM = (NN + 127) / 128;

    // ---- CSR build + precompute ----
    k_init<<<GN, 256>>>();
    k_detect<<<16, 256>>>((const int*)ei);
    k_count<<<GE, 256>>>(ei);
    k_bsum<<<NB, 256>>>();
    k_bscan<<<1, 256>>>();
    k_rowoff<<<NB, 256>>>();
    k_fill<<<GE, 256>>>(ei);
    k_sdeg<<<GN, 256>>>();
    k_matsq<<<(DD * DD + 255) / 256, 256>>>(W1, Wsq1);
    k_matsq<<<(DD * DD + 255) / 256, 256>>>(W2, Wsq2);
    k_wsplit<<<(DD * DD + 255) / 256, 256>>>(Wsq1, Whl1, DD * DD);
    k_wsplit<<<(DD * DD + 255) / 256, 256>>>(Wsq2, Whl2, DD * DD);
    k_wsplit<<<(DD * OUTD + 255) / 256, 256>>>(Wout, WhlO, DD * OUTD);
    k_bw<<<1, 128>>>(b1, W1, bW1);
    k_bw<<<1, 128>>>(b2, W2, bW2);

    // ---- Block 1: h1 = relu(A^2(x) @ W1^2 + s*(b1@W1) + d*b1) ----
    k_agg<<<GAG, 256>>>(x, bufA);
    k_agg<<<GAG, 256>>>(bufA, bufB);
    k_gemm_tc<128, true><<<GGM, 256, SM128>>>(bufB, Whl1, sdeg, degv, bW1, b1, bufA);

    // ---- Block 2: h2 = relu(A^2(h1) @ W2^2 + s*(b2@W2) + d*b2) ----
    k_agg<<<GAG, 256>>>(bufA, bufB);
    k_agg<<<GAG, 256>>>(bufB, bufA);
    k_gemm_tc<128, true><<<GGM, 256, SM128>>>(bufA, Whl2, sdeg, degv, bW2, b2, bufB);

    // ---- Output: out = h2 @ Wout + bout ----
    k_gemm_tc<64, false><<<GGM, 256, SM64>>>(bufB, WhlO, nullptr, nullptr,
                                             nullptr, bout, out);
}